// round 7
// baseline (speedup 1.0000x reference)
#include <cuda_runtime.h>
#include <math.h>
#include <stdint.h>

// Problem dims (fixed by the dataset)
#define BB 4
#define LL 2048
#define DD 2048
#define RR 2560
#define MM (BB * LL)      // 8192
#define K4 (4 * RR)       // 10240 (conv fused-K)

// ---------------------------------------------------------------------------
// Device scratch
// ---------------------------------------------------------------------------
__device__ float g_W1r[(size_t)RR * DD];
__device__ float g_Wg [(size_t)2 * RR * RR];
__device__ float g_W2r[(size_t)DD * RR];
__device__ float g_Wc2[(size_t)RR * K4];
__device__ float g_Xr [(size_t)MM * DD];
__device__ float g_H1 [(size_t)MM * RR];
__device__ float g_HC [(size_t)MM * RR];
__device__ float g_G  [(size_t)MM * 2 * RR];
__device__ float g_Ga [(size_t)MM * RR];
__device__ float g_Gb [(size_t)MM * RR];
__device__ float g_CA [(size_t)BB * 32 * RR];   // chunk carry A-products
__device__ float g_CB [(size_t)BB * 32 * RR];   // chunk carry B / carry-in
__device__ float g_sp [RR];

// ---------------------------------------------------------------------------
// helpers / PTX  (base ISA only: mma.sync + cp.async — sm_103 non-'a' safe)
// ---------------------------------------------------------------------------
__device__ __forceinline__ float tf32r(float x) {
    uint32_t u;
    asm("cvt.rna.tf32.f32 %0, %1;" : "=r"(u) : "f"(x));
    return __uint_as_float(u);
}
__device__ __forceinline__ void cpa16(uint32_t dst, const void* src, int sz) {
    asm volatile("cp.async.cg.shared.global [%0], [%1], 16, %2;\n"
                 :: "r"(dst), "l"(src), "r"(sz));
}
__device__ __forceinline__ void mma_tf32(float* c, const uint32_t* a, const uint32_t* b) {
    asm volatile(
        "mma.sync.aligned.m16n8k8.row.col.f32.tf32.tf32.f32 "
        "{%0,%1,%2,%3}, {%4,%5,%6,%7}, {%8,%9}, {%0,%1,%2,%3};\n"
        : "+f"(c[0]), "+f"(c[1]), "+f"(c[2]), "+f"(c[3])
        : "r"(a[0]), "r"(a[1]), "r"(a[2]), "r"(a[3]), "r"(b[0]), "r"(b[1]));
}

// ---------------------------------------------------------------------------
// tf32 tensor-core TN GEMM: C[M,N] = A[M,K] @ W[N,K]^T (+bias)(epilogue)
// CTA tile 128(M) x 256(N) x 32(K), 256 threads = 8 warps (2m x 4n),
// warp tile 64x64 (4x8 m16n8k8), 3-stage cp.async pipeline.
// CONV: A is a 4-tap time-shifted view of H1 (K=4*RR, lda=RR), zero-padded.
// EPI: 0=none, 1=SiLU+tf32 round, 2=tf32 round.
// ---------------------------------------------------------------------------
#define TBN 256
#define LDA_ 36                        // padded lead dim (floats)
#define A_FLOATS (128 * LDA_)          // 4608
#define B_FLOATS (TBN * LDA_)          // 9216
#define STAGE_FLOATS (A_FLOATS + B_FLOATS)
#define STAGE_BYTES  (STAGE_FLOATS * 4)          // 55296
#define GSMEM_TOTAL  (3 * STAGE_BYTES)           // 165888

template<int EPI, bool BIAS, bool CONV>
__global__ __launch_bounds__(256, 1)
void gemm_mma(const float* __restrict__ A, const float* __restrict__ W,
              const float* __restrict__ bias, float* __restrict__ C,
              int N, int K, int lda)
{
    extern __shared__ float sm[];
    const uint32_t smb = (uint32_t)__cvta_generic_to_shared(sm);

    const int tid  = threadIdx.x;
    const int lane = tid & 31;
    const int wid  = tid >> 5;
    const int g    = lane >> 2;         // 0..7
    const int tq   = lane & 3;          // 0..3
    const int wm   = (wid >> 2) << 6;   // 0 / 64
    const int wn   = (wid & 3) << 6;    // 0,64,128,192
    const int bm   = blockIdx.y * 128;
    const int bn   = blockIdx.x * TBN;

    float acc[4][8][4];
#pragma unroll
    for (int i = 0; i < 4; i++)
#pragma unroll
        for (int j = 0; j < 8; j++)
#pragma unroll
            for (int c = 0; c < 4; c++) acc[i][j][c] = 0.f;

    const int KT = K / 32;

    auto issue = [&](int kt, int st) {
        const int k0 = kt * 32;
        int tap = 0, shift = 0, kcol = k0;
        if (CONV) { tap = k0 / RR; kcol = k0 - tap * RR; shift = 2 * tap - 3; }
        const uint32_t abase = smb + st * STAGE_BYTES;
        const uint32_t bbase = abase + A_FLOATS * 4;
        // A: 128 rows x 32 floats  (1024 x 16B)
#pragma unroll
        for (int i = 0; i < 4; i++) {
            int idx = tid + i * 256;
            int row = idx >> 3, seg = idx & 7;
            int m = bm + row, arow = m, sz = 16;
            if (CONV) {
                int t  = m & (LL - 1);
                int ts = t + shift;
                if ((unsigned)ts < (unsigned)LL) arow = m - t + ts;
                else                             sz = 0;     // zero-fill pad row
            }
            cpa16(abase + (uint32_t)((row * LDA_ + seg * 4) * 4),
                  A + (size_t)arow * lda + kcol + seg * 4, sz);
        }
        // B: 256 rows x 32 floats  (2048 x 16B)
#pragma unroll
        for (int i = 0; i < 8; i++) {
            int idx = tid + i * 256;
            int row = idx >> 3, seg = idx & 7;
            cpa16(bbase + (uint32_t)((row * LDA_ + seg * 4) * 4),
                  W + (size_t)(bn + row) * K + k0 + seg * 4, 16);
        }
        asm volatile("cp.async.commit_group;\n");
    };

    issue(0, 0); issue(1, 1); issue(2, 2);

    for (int kt = 0; kt < KT; kt++) {
        const int st = kt % 3;
        if (kt < KT - 2)       asm volatile("cp.async.wait_group 2;\n");
        else if (kt == KT - 2) asm volatile("cp.async.wait_group 1;\n");
        else                   asm volatile("cp.async.wait_group 0;\n");
        __syncthreads();

        const float* As = sm + st * STAGE_FLOATS;
        const float* Bs = As + A_FLOATS;

#pragma unroll
        for (int s8 = 0; s8 < 4; s8++) {
            const int kk = s8 * 8 + tq;
            uint32_t af[4][4], bf[8][2];
#pragma unroll
            for (int nt = 0; nt < 8; nt++) {
                const float* bp = Bs + (wn + nt * 8 + g) * LDA_ + kk;
                bf[nt][0] = __float_as_uint(bp[0]);
                bf[nt][1] = __float_as_uint(bp[4]);
            }
#pragma unroll
            for (int mt = 0; mt < 4; mt++) {
                const float* ap = As + (wm + mt * 16 + g) * LDA_ + kk;
                af[mt][0] = __float_as_uint(ap[0]);
                af[mt][1] = __float_as_uint(ap[8 * LDA_]);
                af[mt][2] = __float_as_uint(ap[4]);
                af[mt][3] = __float_as_uint(ap[8 * LDA_ + 4]);
            }
#pragma unroll
            for (int mt = 0; mt < 4; mt++)
#pragma unroll
                for (int nt = 0; nt < 8; nt++)
                    mma_tf32(acc[mt][nt], af[mt], bf[nt]);
        }
        __syncthreads();

        const int kn = kt + 3;
        if (kn < KT) issue(kn, st);
    }

    // Epilogue: c0,c1 -> (row g, col tq*2..+1); c2,c3 -> row g+8
#pragma unroll
    for (int mt = 0; mt < 4; mt++) {
        const int r0 = bm + wm + mt * 16 + g;
#pragma unroll
        for (int nt = 0; nt < 8; nt++) {
            const int col = bn + wn + nt * 8 + tq * 2;
            float bx_ = 0.f, by_ = 0.f;
            if (BIAS) { float2 bb = *(const float2*)(bias + col); bx_ = bb.x; by_ = bb.y; }
            float v[4] = { acc[mt][nt][0] + bx_, acc[mt][nt][1] + by_,
                           acc[mt][nt][2] + bx_, acc[mt][nt][3] + by_ };
            if (EPI == 1) {
#pragma unroll
                for (int j = 0; j < 4; j++) {
                    float z = v[j];
                    z = z / (1.f + __expf(-z));
                    v[j] = tf32r(z);
                }
            } else if (EPI == 2) {
#pragma unroll
                for (int j = 0; j < 4; j++) v[j] = tf32r(v[j]);
            }
            *(float2*)(C + (size_t)r0 * N + col)       = make_float2(v[0], v[1]);
            *(float2*)(C + (size_t)(r0 + 8) * N + col) = make_float2(v[2], v[3]);
        }
    }
}

// ---------------------------------------------------------------------------
// prep / elementwise kernels
// ---------------------------------------------------------------------------
__global__ void round_copy(const float* __restrict__ in, float* __restrict__ out, int n)
{
    int i = blockIdx.x * 256 + threadIdx.x;
    if (i < n) out[i] = tf32r(in[i]);
}

__global__ void conv_pack(const float* __restrict__ cw, float* __restrict__ wc2)
{
    int idx = blockIdx.x * 256 + threadIdx.x;
    int o   = idx / K4;
    int rem = idx - o * K4;
    int t   = rem / RR;
    int i   = rem - t * RR;
    wc2[idx] = tf32r(cw[((size_t)o * RR + i) * 4 + t]);
}

__global__ void prep_sp(const float* __restrict__ lam, float* __restrict__ sp)
{
    int d = blockIdx.x * 256 + threadIdx.x;
    if (d < RR) {
        float l = lam[d];
        float s = (l > 20.f) ? l : log1pf(expf(l));
        sp[d] = -8.f * s;
    }
}

__global__ void gate2(const float* __restrict__ G, const float* __restrict__ hc,
                      const float* __restrict__ ba, const float* __restrict__ bx,
                      const float* __restrict__ sp,
                      float* __restrict__ av, float* __restrict__ bv)
{
    int idx = blockIdx.x * 256 + threadIdx.x;
    int m = idx / RR;
    int d = idx - m * RR;
    float rl = G[(size_t)m * (2 * RR) + d]      + ba[d];
    float il = G[(size_t)m * (2 * RR) + RR + d] + bx[d];
    float r  = 1.f / (1.f + __expf(-rl));
    float ig = 1.f / (1.f + __expf(-il));
    float a  = __expf(sp[d] * r);
    float mult = sqrtf(fmaxf(1.f - a * a, 0.f));
    av[idx] = a;
    bv[idx] = mult * ig * hc[idx];
}

// ---- 3-phase chunked scan: L=2048 -> 32 chunks x 64 steps ----
#define SCH 32
#define SCL 64

__global__ void scan_p1(const float* __restrict__ a, const float* __restrict__ bv,
                        float* __restrict__ CA, float* __restrict__ CB)
{
    int gid = blockIdx.x * 256 + threadIdx.x;          // BB*SCH*RR total
    int b   = gid / (SCH * RR);
    int rem = gid - b * (SCH * RR);
    int c   = rem / RR;
    int d   = rem - c * RR;
    size_t base = ((size_t)b * LL + (size_t)c * SCL) * RR + d;
    float Ap = 1.f, h = 0.f;
#pragma unroll 4
    for (int t = 0; t < SCL; t++) {
        size_t off = base + (size_t)t * RR;
        float at = a[off];
        Ap *= at;
        h = fmaf(at, h, bv[off]);
    }
    CA[gid] = Ap;
    CB[gid] = h;
}

__global__ void scan_p2(float* __restrict__ CA, float* __restrict__ CB)
{
    int gid = blockIdx.x * 256 + threadIdx.x;          // BB*RR total
    int b = gid / RR;
    int d = gid - b * RR;
    float h = 0.f;
#pragma unroll
    for (int c = 0; c < SCH; c++) {
        size_t idx = ((size_t)b * SCH + c) * RR + d;
        float A = CA[idx], Bv = CB[idx];
        CB[idx] = h;                 // carry-in for chunk c
        h = fmaf(A, h, Bv);
    }
}

__global__ void scan_p3(const float* __restrict__ a, const float* __restrict__ bv,
                        const float* __restrict__ CB, float* __restrict__ h)
{
    int gid = blockIdx.x * 256 + threadIdx.x;
    int b   = gid / (SCH * RR);
    int rem = gid - b * (SCH * RR);
    int c   = rem / RR;
    int d   = rem - c * RR;
    size_t base = ((size_t)b * LL + (size_t)c * SCL) * RR + d;
    float hp = CB[gid];
#pragma unroll 4
    for (int t = 0; t < SCL; t++) {
        size_t off = base + (size_t)t * RR;
        hp = fmaf(a[off], hp, bv[off]);
        h[off] = tf32r(hp);
    }
}

// ---------------------------------------------------------------------------
extern "C" void kernel_launch(void* const* d_in, const int* in_sizes, int n_in,
                              void* d_out, int out_size)
{
    const float* x      = (const float*)d_in[0];
    const float* w1     = (const float*)d_in[1];
    const float* b1     = (const float*)d_in[2];
    const float* conv_w = (const float*)d_in[3];
    const float* conv_b = (const float*)d_in[4];
    const float* wa     = (const float*)d_in[5];
    const float* ba     = (const float*)d_in[6];
    const float* wx     = (const float*)d_in[7];
    const float* bx     = (const float*)d_in[8];
    const float* lam    = (const float*)d_in[9];
    const float* w2     = (const float*)d_in[10];
    const float* b2     = (const float*)d_in[11];
    float* out = (float*)d_out;

    float *W1r, *Wg, *W2r, *Wc2, *Xr, *H1, *HC, *G, *Ga, *Gb, *CA, *CB, *sp;
    cudaGetSymbolAddress((void**)&W1r, g_W1r);
    cudaGetSymbolAddress((void**)&Wg,  g_Wg);
    cudaGetSymbolAddress((void**)&W2r, g_W2r);
    cudaGetSymbolAddress((void**)&Wc2, g_Wc2);
    cudaGetSymbolAddress((void**)&Xr,  g_Xr);
    cudaGetSymbolAddress((void**)&H1,  g_H1);
    cudaGetSymbolAddress((void**)&HC,  g_HC);
    cudaGetSymbolAddress((void**)&G,   g_G);
    cudaGetSymbolAddress((void**)&Ga,  g_Ga);
    cudaGetSymbolAddress((void**)&Gb,  g_Gb);
    cudaGetSymbolAddress((void**)&CA,  g_CA);
    cudaGetSymbolAddress((void**)&CB,  g_CB);
    cudaGetSymbolAddress((void**)&sp,  g_sp);

    cudaFuncSetAttribute(gemm_mma<1, true,  false>, cudaFuncAttributeMaxDynamicSharedMemorySize, GSMEM_TOTAL);
    cudaFuncSetAttribute(gemm_mma<2, true,  true >, cudaFuncAttributeMaxDynamicSharedMemorySize, GSMEM_TOTAL);
    cudaFuncSetAttribute(gemm_mma<0, false, false>, cudaFuncAttributeMaxDynamicSharedMemorySize, GSMEM_TOTAL);
    cudaFuncSetAttribute(gemm_mma<0, true,  false>, cudaFuncAttributeMaxDynamicSharedMemorySize, GSMEM_TOTAL);

    // prep: RN-round every MMA input once
    round_copy<<<(RR * DD + 255) / 256, 256>>>(w1, W1r, RR * DD);
    round_copy<<<(RR * RR + 255) / 256, 256>>>(wa, Wg,                   RR * RR);
    round_copy<<<(RR * RR + 255) / 256, 256>>>(wx, Wg + (size_t)RR * RR, RR * RR);
    round_copy<<<(DD * RR + 255) / 256, 256>>>(w2, W2r, DD * RR);
    round_copy<<<(MM * DD + 255) / 256, 256>>>(x,  Xr,  MM * DD);
    conv_pack<<<((size_t)RR * K4) / 256, 256>>>(conv_w, Wc2);
    prep_sp<<<(RR + 255) / 256, 256>>>(lam, sp);

    dim3 blk(256);
    dim3 gN2560(RR / TBN,     MM / 128);   // 10 x 64
    dim3 gN5120(2 * RR / TBN, MM / 128);   // 20 x 64
    dim3 gN2048(DD / TBN,     MM / 128);   //  8 x 64

    // 1) H1 = tf32( silu(x @ w1^T + b1) )
    gemm_mma<1, true,  false><<<gN2560, blk, GSMEM_TOTAL>>>(Xr, W1r, b1, H1, RR, DD, DD);
    // 2) HC = tf32( conv(H1) + conv_b )  — single fused GEMM, K = 4*R
    gemm_mma<2, true,  true ><<<gN2560, blk, GSMEM_TOTAL>>>(H1, Wc2, conv_b, HC, RR, K4, RR);
    // 3) G = HC @ [wa;wx]^T
    gemm_mma<0, false, false><<<gN5120, blk, GSMEM_TOTAL>>>(HC, Wg, nullptr, G, 2 * RR, RR, RR);
    // 4) a/b for RG-LRU
    gate2<<<((size_t)MM * RR) / 256, 256>>>(G, HC, ba, bx, sp, Ga, Gb);
    // 5) chunked parallel scan -> h (into H1)
    scan_p1<<<(BB * SCH * RR) / 256, 256>>>(Ga, Gb, CA, CB);
    scan_p2<<<(BB * RR) / 256, 256>>>(CA, CB);
    scan_p3<<<(BB * SCH * RR) / 256, 256>>>(Ga, Gb, CB, H1);
    // 6) out = h @ w2^T + b2
    gemm_mma<0, true,  false><<<gN2048, blk, GSMEM_TOTAL>>>(H1, W2r, b2, out, DD, RR, RR);
}

// round 8
// speedup vs baseline: 1.8377x; 1.8377x over previous
#include <cuda_runtime.h>
#include <cuda_fp16.h>
#include <math.h>
#include <stdint.h>

// Problem dims (fixed by the dataset)
#define BB 4
#define LL 2048
#define DD 2048
#define RR 2560
#define MM (BB * LL)      // 8192
#define K4 (4 * RR)       // 10240 (conv fused-K)

// ---------------------------------------------------------------------------
// Device scratch
// ---------------------------------------------------------------------------
__device__ __half g_W1h[(size_t)RR * DD];
__device__ __half g_Wgh[(size_t)2 * RR * RR];
__device__ __half g_W2h[(size_t)DD * RR];
__device__ __half g_Wch[(size_t)RR * K4];
__device__ __half g_Xh [(size_t)MM * DD];
__device__ __half g_H1h[(size_t)MM * RR];     // silu out; later reused for scan h
__device__ __half g_HCh[(size_t)MM * RR];     // conv out
__device__ float  g_G  [(size_t)MM * 2 * RR]; // gate pre-activations (f32)
__device__ float  g_Ga [(size_t)MM * RR];
__device__ float  g_Gb [(size_t)MM * RR];
__device__ float  g_CA [(size_t)BB * 32 * RR];
__device__ float  g_CB [(size_t)BB * 32 * RR];
__device__ float  g_sp [RR];

// ---------------------------------------------------------------------------
// helpers / PTX  (base ISA only: mma.sync fp16 + cp.async)
// ---------------------------------------------------------------------------
__device__ __forceinline__ void cpa16(uint32_t dst, const void* src, int sz) {
    asm volatile("cp.async.cg.shared.global [%0], [%1], 16, %2;\n"
                 :: "r"(dst), "l"(src), "r"(sz));
}
__device__ __forceinline__ void mma_f16(float* c, const uint32_t* a, const uint32_t* b) {
    asm volatile(
        "mma.sync.aligned.m16n8k16.row.col.f32.f16.f16.f32 "
        "{%0,%1,%2,%3}, {%4,%5,%6,%7}, {%8,%9}, {%0,%1,%2,%3};\n"
        : "+f"(c[0]), "+f"(c[1]), "+f"(c[2]), "+f"(c[3])
        : "r"(a[0]), "r"(a[1]), "r"(a[2]), "r"(a[3]), "r"(b[0]), "r"(b[1]));
}

// ---------------------------------------------------------------------------
// fp16 tensor-core TN GEMM: C[M,N] = A[M,K] @ W[N,K]^T (+bias)(epilogue)
// CTA tile 128(M) x 256(N) x 64(K halves), 256 threads = 8 warps (2m x 4n),
// warp tile 64x64 (4x8 m16n8k16), 3-stage cp.async pipeline.
// CONV: A is a 4-tap time-shifted view of H1 (K=4*RR, lda=RR), zero-padded.
// EPI: 0=none, 1=SiLU.  TOUT: __half or float.
// ---------------------------------------------------------------------------
#define TBN 256
#define TKH 64                          // K halves per tile (=128B rows)
#define LDH 72                          // padded lead dim (halves), 144B
#define A_HALVES (128 * LDH)            // 9216
#define B_HALVES (TBN * LDH)            // 18432
#define STAGE_HALVES (A_HALVES + B_HALVES)
#define STAGE_BYTES  (STAGE_HALVES * 2)          // 55296
#define GSMEM_TOTAL  (3 * STAGE_BYTES)           // 165888

template<int EPI, bool BIAS, bool CONV, typename TOUT>
__global__ __launch_bounds__(256, 1)
void gemm_mma(const __half* __restrict__ A, const __half* __restrict__ W,
              const float* __restrict__ bias, TOUT* __restrict__ C,
              int N, int K, int lda)
{
    extern __shared__ __half sm[];
    const uint32_t smb = (uint32_t)__cvta_generic_to_shared(sm);

    const int tid  = threadIdx.x;
    const int lane = tid & 31;
    const int wid  = tid >> 5;
    const int g    = lane >> 2;         // 0..7
    const int tq   = lane & 3;          // 0..3
    const int wm   = (wid >> 2) << 6;   // 0 / 64
    const int wn   = (wid & 3) << 6;    // 0,64,128,192
    const int bm   = blockIdx.y * 128;
    const int bn   = blockIdx.x * TBN;

    float acc[4][8][4];
#pragma unroll
    for (int i = 0; i < 4; i++)
#pragma unroll
        for (int j = 0; j < 8; j++)
#pragma unroll
            for (int c = 0; c < 4; c++) acc[i][j][c] = 0.f;

    const int KT = K / TKH;

    auto issue = [&](int kt, int st) {
        const int k0 = kt * TKH;
        int tap = 0, shift = 0, kcol = k0;
        if (CONV) { tap = k0 / RR; kcol = k0 - tap * RR; shift = 2 * tap - 3; }
        const uint32_t abase = smb + st * STAGE_BYTES;
        const uint32_t bbase = abase + A_HALVES * 2;
        // A: 128 rows x 64 halves (128B) -> 1024 x 16B
#pragma unroll
        for (int i = 0; i < 4; i++) {
            int idx = tid + i * 256;
            int row = idx >> 3, seg = idx & 7;
            int m = bm + row, arow = m, sz = 16;
            if (CONV) {
                int t  = m & (LL - 1);
                int ts = t + shift;
                if ((unsigned)ts < (unsigned)LL) arow = m - t + ts;
                else                             sz = 0;     // zero-fill pad row
            }
            cpa16(abase + (uint32_t)(row * (LDH * 2) + seg * 16),
                  A + (size_t)arow * lda + kcol + seg * 8, sz);
        }
        // B: 256 rows x 64 halves -> 2048 x 16B
#pragma unroll
        for (int i = 0; i < 8; i++) {
            int idx = tid + i * 256;
            int row = idx >> 3, seg = idx & 7;
            cpa16(bbase + (uint32_t)(row * (LDH * 2) + seg * 16),
                  W + (size_t)(bn + row) * K + k0 + seg * 8, 16);
        }
        asm volatile("cp.async.commit_group;\n");
    };

    issue(0, 0); issue(1, 1); issue(2, 2);

    for (int kt = 0; kt < KT; kt++) {
        const int st = kt % 3;
        if (kt < KT - 2)       asm volatile("cp.async.wait_group 2;\n");
        else if (kt == KT - 2) asm volatile("cp.async.wait_group 1;\n");
        else                   asm volatile("cp.async.wait_group 0;\n");
        __syncthreads();

        const __half* As = sm + st * STAGE_HALVES;
        const __half* Bs = As + A_HALVES;

#pragma unroll
        for (int s16 = 0; s16 < 4; s16++) {
            const int kk = s16 * 16 + tq * 2;   // half index (even -> 4B aligned)
            uint32_t af[4][4], bf[8][2];
#pragma unroll
            for (int nt = 0; nt < 8; nt++) {
                const __half* bp = Bs + (wn + nt * 8 + g) * LDH + kk;
                bf[nt][0] = *(const uint32_t*)(bp);
                bf[nt][1] = *(const uint32_t*)(bp + 8);
            }
#pragma unroll
            for (int mt = 0; mt < 4; mt++) {
                const __half* ap = As + (wm + mt * 16 + g) * LDH + kk;
                af[mt][0] = *(const uint32_t*)(ap);
                af[mt][1] = *(const uint32_t*)(ap + 8 * LDH);
                af[mt][2] = *(const uint32_t*)(ap + 8);
                af[mt][3] = *(const uint32_t*)(ap + 8 * LDH + 8);
            }
#pragma unroll
            for (int mt = 0; mt < 4; mt++)
#pragma unroll
                for (int nt = 0; nt < 8; nt++)
                    mma_f16(acc[mt][nt], af[mt], bf[nt]);
        }
        __syncthreads();

        const int kn = kt + 3;
        if (kn < KT) issue(kn, st);
    }

    // Epilogue: c0,c1 -> (row g, col tq*2..+1); c2,c3 -> row g+8
#pragma unroll
    for (int mt = 0; mt < 4; mt++) {
        const int r0 = bm + wm + mt * 16 + g;
#pragma unroll
        for (int nt = 0; nt < 8; nt++) {
            const int col = bn + wn + nt * 8 + tq * 2;
            float bx_ = 0.f, by_ = 0.f;
            if (BIAS) { float2 bb = *(const float2*)(bias + col); bx_ = bb.x; by_ = bb.y; }
            float v[4] = { acc[mt][nt][0] + bx_, acc[mt][nt][1] + by_,
                           acc[mt][nt][2] + bx_, acc[mt][nt][3] + by_ };
            if (EPI == 1) {
#pragma unroll
                for (int j = 0; j < 4; j++) v[j] = v[j] / (1.f + __expf(-v[j]));
            }
            if (sizeof(TOUT) == 2) {
                __half2* c0 = (__half2*)((__half*)C + (size_t)r0 * N + col);
                __half2* c1 = (__half2*)((__half*)C + (size_t)(r0 + 8) * N + col);
                *c0 = __floats2half2_rn(v[0], v[1]);
                *c1 = __floats2half2_rn(v[2], v[3]);
            } else {
                *(float2*)((float*)C + (size_t)r0 * N + col)       = make_float2(v[0], v[1]);
                *(float2*)((float*)C + (size_t)(r0 + 8) * N + col) = make_float2(v[2], v[3]);
            }
        }
    }
}

// ---------------------------------------------------------------------------
// prep / elementwise kernels
// ---------------------------------------------------------------------------
__global__ void half_copy(const float* __restrict__ in, __half* __restrict__ out, int n)
{
    int i = blockIdx.x * 256 + threadIdx.x;
    if (i < n) out[i] = __float2half_rn(in[i]);
}

__global__ void conv_pack(const float* __restrict__ cw, __half* __restrict__ wch)
{
    int idx = blockIdx.x * 256 + threadIdx.x;
    int o   = idx / K4;
    int rem = idx - o * K4;
    int t   = rem / RR;
    int i   = rem - t * RR;
    wch[idx] = __float2half_rn(cw[((size_t)o * RR + i) * 4 + t]);
}

__global__ void prep_sp(const float* __restrict__ lam, float* __restrict__ sp)
{
    int d = blockIdx.x * 256 + threadIdx.x;
    if (d < RR) {
        float l = lam[d];
        float s = (l > 20.f) ? l : log1pf(expf(l));
        sp[d] = -8.f * s;
    }
}

__global__ void gate2(const float* __restrict__ G, const __half* __restrict__ hc,
                      const float* __restrict__ ba, const float* __restrict__ bx,
                      const float* __restrict__ sp,
                      float* __restrict__ av, float* __restrict__ bv)
{
    int idx = blockIdx.x * 256 + threadIdx.x;
    int m = idx / RR;
    int d = idx - m * RR;
    float rl = G[(size_t)m * (2 * RR) + d]      + ba[d];
    float il = G[(size_t)m * (2 * RR) + RR + d] + bx[d];
    float r  = 1.f / (1.f + __expf(-rl));
    float ig = 1.f / (1.f + __expf(-il));
    float a  = __expf(sp[d] * r);
    float mult = sqrtf(fmaxf(1.f - a * a, 0.f));
    av[idx] = a;
    bv[idx] = mult * ig * __half2float(hc[idx]);
}

// ---- 3-phase chunked scan: L=2048 -> 32 chunks x 64 steps ----
#define SCH 32
#define SCL 64

__global__ void scan_p1(const float* __restrict__ a, const float* __restrict__ bv,
                        float* __restrict__ CA, float* __restrict__ CB)
{
    int gid = blockIdx.x * 256 + threadIdx.x;          // BB*SCH*RR total
    int b   = gid / (SCH * RR);
    int rem = gid - b * (SCH * RR);
    int c   = rem / RR;
    int d   = rem - c * RR;
    size_t base = ((size_t)b * LL + (size_t)c * SCL) * RR + d;
    float Ap = 1.f, h = 0.f;
#pragma unroll 4
    for (int t = 0; t < SCL; t++) {
        size_t off = base + (size_t)t * RR;
        float at = a[off];
        Ap *= at;
        h = fmaf(at, h, bv[off]);
    }
    CA[gid] = Ap;
    CB[gid] = h;
}

__global__ void scan_p2(float* __restrict__ CA, float* __restrict__ CB)
{
    int gid = blockIdx.x * 256 + threadIdx.x;          // BB*RR total
    int b = gid / RR;
    int d = gid - b * RR;
    float h = 0.f;
#pragma unroll
    for (int c = 0; c < SCH; c++) {
        size_t idx = ((size_t)b * SCH + c) * RR + d;
        float A = CA[idx], Bv = CB[idx];
        CB[idx] = h;                 // carry-in for chunk c
        h = fmaf(A, h, Bv);
    }
}

__global__ void scan_p3(const float* __restrict__ a, const float* __restrict__ bv,
                        const float* __restrict__ CB, __half* __restrict__ h)
{
    int gid = blockIdx.x * 256 + threadIdx.x;
    int b   = gid / (SCH * RR);
    int rem = gid - b * (SCH * RR);
    int c   = rem / RR;
    int d   = rem - c * RR;
    size_t base = ((size_t)b * LL + (size_t)c * SCL) * RR + d;
    float hp = CB[gid];
#pragma unroll 4
    for (int t = 0; t < SCL; t++) {
        size_t off = base + (size_t)t * RR;
        hp = fmaf(a[off], hp, bv[off]);
        h[off] = __float2half_rn(hp);
    }
}

// ---------------------------------------------------------------------------
extern "C" void kernel_launch(void* const* d_in, const int* in_sizes, int n_in,
                              void* d_out, int out_size)
{
    const float* x      = (const float*)d_in[0];
    const float* w1     = (const float*)d_in[1];
    const float* b1     = (const float*)d_in[2];
    const float* conv_w = (const float*)d_in[3];
    const float* conv_b = (const float*)d_in[4];
    const float* wa     = (const float*)d_in[5];
    const float* ba     = (const float*)d_in[6];
    const float* wx     = (const float*)d_in[7];
    const float* bx     = (const float*)d_in[8];
    const float* lam    = (const float*)d_in[9];
    const float* w2     = (const float*)d_in[10];
    const float* b2     = (const float*)d_in[11];
    float* out = (float*)d_out;

    __half *W1h, *Wgh, *W2h, *Wch, *Xh, *H1h, *HCh;
    float  *G, *Ga, *Gb, *CA, *CB, *sp;
    cudaGetSymbolAddress((void**)&W1h, g_W1h);
    cudaGetSymbolAddress((void**)&Wgh, g_Wgh);
    cudaGetSymbolAddress((void**)&W2h, g_W2h);
    cudaGetSymbolAddress((void**)&Wch, g_Wch);
    cudaGetSymbolAddress((void**)&Xh,  g_Xh);
    cudaGetSymbolAddress((void**)&H1h, g_H1h);
    cudaGetSymbolAddress((void**)&HCh, g_HCh);
    cudaGetSymbolAddress((void**)&G,   g_G);
    cudaGetSymbolAddress((void**)&Ga,  g_Ga);
    cudaGetSymbolAddress((void**)&Gb,  g_Gb);
    cudaGetSymbolAddress((void**)&CA,  g_CA);
    cudaGetSymbolAddress((void**)&CB,  g_CB);
    cudaGetSymbolAddress((void**)&sp,  g_sp);

    cudaFuncSetAttribute(gemm_mma<1, true,  false, __half>, cudaFuncAttributeMaxDynamicSharedMemorySize, GSMEM_TOTAL);
    cudaFuncSetAttribute(gemm_mma<0, true,  true,  __half>, cudaFuncAttributeMaxDynamicSharedMemorySize, GSMEM_TOTAL);
    cudaFuncSetAttribute(gemm_mma<0, false, false, float >, cudaFuncAttributeMaxDynamicSharedMemorySize, GSMEM_TOTAL);
    cudaFuncSetAttribute(gemm_mma<0, true,  false, float >, cudaFuncAttributeMaxDynamicSharedMemorySize, GSMEM_TOTAL);

    // prep: RN-round every MMA input to fp16 once
    half_copy<<<(RR * DD + 255) / 256, 256>>>(w1, W1h, RR * DD);
    half_copy<<<(RR * RR + 255) / 256, 256>>>(wa, Wgh,                   RR * RR);
    half_copy<<<(RR * RR + 255) / 256, 256>>>(wx, Wgh + (size_t)RR * RR, RR * RR);
    half_copy<<<(DD * RR + 255) / 256, 256>>>(w2, W2h, DD * RR);
    half_copy<<<(MM * DD + 255) / 256, 256>>>(x,  Xh,  MM * DD);
    conv_pack<<<((size_t)RR * K4) / 256, 256>>>(conv_w, Wch);
    prep_sp<<<(RR + 255) / 256, 256>>>(lam, sp);

    dim3 blk(256);
    dim3 gN2560(RR / TBN,     MM / 128);   // 10 x 64
    dim3 gN5120(2 * RR / TBN, MM / 128);   // 20 x 64
    dim3 gN2048(DD / TBN,     MM / 128);   //  8 x 64

    // 1) H1 = h( silu(x @ w1^T + b1) )
    gemm_mma<1, true,  false, __half><<<gN2560, blk, GSMEM_TOTAL>>>(Xh, W1h, b1, H1h, RR, DD, DD);
    // 2) HC = h( conv(H1) + conv_b )  — single fused GEMM, K = 4*R
    gemm_mma<0, true,  true,  __half><<<gN2560, blk, GSMEM_TOTAL>>>(H1h, Wch, conv_b, HCh, RR, K4, RR);
    // 3) G = HC @ [wa;wx]^T  (f32 out; biases added in gate2)
    gemm_mma<0, false, false, float ><<<gN5120, blk, GSMEM_TOTAL>>>(HCh, Wgh, nullptr, G, 2 * RR, RR, RR);
    // 4) a/b for RG-LRU (f32)
    gate2<<<((size_t)MM * RR) / 256, 256>>>(G, HCh, ba, bx, sp, Ga, Gb);
    // 5) chunked parallel scan -> h (half, into H1h)
    scan_p1<<<(BB * SCH * RR) / 256, 256>>>(Ga, Gb, CA, CB);
    scan_p2<<<(BB * RR) / 256, 256>>>(CA, CB);
    scan_p3<<<(BB * SCH * RR) / 256, 256>>>(Ga, Gb, CB, H1h);
    // 6) out = h @ w2^T + b2  (f32)
    gemm_mma<0, true,  false, float ><<<gN2048, blk, GSMEM_TOTAL>>>(H1h, W2h, b2, out, DD, RR, RR);
}

// round 9
// speedup vs baseline: 1.9931x; 1.0845x over previous
#include <cuda_runtime.h>
#include <cuda_fp16.h>
#include <math.h>
#include <stdint.h>

// Problem dims (fixed by the dataset)
#define BB 4
#define LL 2048
#define DD 2048
#define RR 2560
#define MM (BB * LL)      // 8192
#define K4 (4 * RR)       // 10240 (conv fused-K)

// ---------------------------------------------------------------------------
// Device scratch
// ---------------------------------------------------------------------------
__device__ __half g_W1h[(size_t)RR * DD];
__device__ __half g_Wgh[(size_t)2 * RR * RR];  // interleaved: row 2d=wa_d, 2d+1=wx_d
__device__ __half g_W2h[(size_t)DD * RR];
__device__ __half g_Wch[(size_t)RR * K4];
__device__ __half g_Xh [(size_t)MM * DD];
__device__ __half g_H1h[(size_t)MM * RR];     // silu out; later reused for scan h
__device__ __half g_HCh[(size_t)MM * RR];     // conv out
__device__ float  g_Ga [(size_t)MM * RR];
__device__ float  g_Gb [(size_t)MM * RR];
__device__ float  g_CA [(size_t)BB * 32 * RR];
__device__ float  g_CB [(size_t)BB * 32 * RR];
__device__ float  g_sp [RR];

// ---------------------------------------------------------------------------
// helpers / PTX  (base ISA only: mma.sync fp16 + cp.async)
// ---------------------------------------------------------------------------
__device__ __forceinline__ void cpa16(uint32_t dst, const void* src, int sz) {
    asm volatile("cp.async.cg.shared.global [%0], [%1], 16, %2;\n"
                 :: "r"(dst), "l"(src), "r"(sz));
}
__device__ __forceinline__ void mma_f16(float* c, const uint32_t* a, const uint32_t* b) {
    asm volatile(
        "mma.sync.aligned.m16n8k16.row.col.f32.f16.f16.f32 "
        "{%0,%1,%2,%3}, {%4,%5,%6,%7}, {%8,%9}, {%0,%1,%2,%3};\n"
        : "+f"(c[0]), "+f"(c[1]), "+f"(c[2]), "+f"(c[3])
        : "r"(a[0]), "r"(a[1]), "r"(a[2]), "r"(a[3]), "r"(b[0]), "r"(b[1]));
}

// ---------------------------------------------------------------------------
// fp16 tensor-core TN GEMM: C[M,N] = A[M,K] @ W[N,K]^T (+bias)(epilogue)
// CTA tile 128(M) x 128(N) x 64(K halves), 256 threads = 8 warps (2m x 4n),
// warp tile 64x32 (4x4 m16n8k16), 3-stage cp.async pipeline, 2 CTAs/SM.
// CONV: A is a 4-tap time-shifted view of H1 (K=4*RR, lda=RR), zero-padded.
// EPI: 0=none, 1=SiLU, 3=fused RG-LRU gate (writes Ga=C and Gb).
// ---------------------------------------------------------------------------
#define TBN 128
#define TKH 64                          // K halves per tile (=128B rows)
#define LDH 72                          // padded lead dim (halves), 144B
#define A_HALVES (128 * LDH)            // 9216
#define B_HALVES (TBN * LDH)            // 9216
#define STAGE_HALVES (A_HALVES + B_HALVES)
#define STAGE_BYTES  (STAGE_HALVES * 2)          // 36864
#define GSMEM_TOTAL  (3 * STAGE_BYTES)           // 110592 -> 2 CTAs/SM

template<int EPI, bool BIAS, bool CONV, typename TOUT>
__global__ __launch_bounds__(256, 2)
void gemm_mma(const __half* __restrict__ A, const __half* __restrict__ W,
              const float* __restrict__ bias, TOUT* __restrict__ C,
              int N, int K, int lda,
              const __half* __restrict__ hcp, const float* __restrict__ spp,
              const float* __restrict__ bap, const float* __restrict__ bxp,
              float* __restrict__ Gb)
{
    extern __shared__ __half sm[];
    const uint32_t smb = (uint32_t)__cvta_generic_to_shared(sm);

    const int tid  = threadIdx.x;
    const int lane = tid & 31;
    const int wid  = tid >> 5;
    const int g    = lane >> 2;         // 0..7
    const int tq   = lane & 3;          // 0..3
    const int wm   = (wid >> 2) << 6;   // 0 / 64
    const int wn   = (wid & 3) << 5;    // 0,32,64,96
    const int bm   = blockIdx.y * 128;
    const int bn   = blockIdx.x * TBN;

    float acc[4][4][4];
#pragma unroll
    for (int i = 0; i < 4; i++)
#pragma unroll
        for (int j = 0; j < 4; j++)
#pragma unroll
            for (int c = 0; c < 4; c++) acc[i][j][c] = 0.f;

    const int KT = K / TKH;

    auto issue = [&](int kt, int st) {
        const int k0 = kt * TKH;
        int tap = 0, shift = 0, kcol = k0;
        if (CONV) { tap = k0 / RR; kcol = k0 - tap * RR; shift = 2 * tap - 3; }
        const uint32_t abase = smb + st * STAGE_BYTES;
        const uint32_t bbase = abase + A_HALVES * 2;
        // A: 128 rows x 64 halves (128B) -> 1024 x 16B
#pragma unroll
        for (int i = 0; i < 4; i++) {
            int idx = tid + i * 256;
            int row = idx >> 3, seg = idx & 7;
            int m = bm + row, arow = m, sz = 16;
            if (CONV) {
                int t  = m & (LL - 1);
                int ts = t + shift;
                if ((unsigned)ts < (unsigned)LL) arow = m - t + ts;
                else                             sz = 0;     // zero-fill pad row
            }
            cpa16(abase + (uint32_t)(row * (LDH * 2) + seg * 16),
                  A + (size_t)arow * lda + kcol + seg * 8, sz);
        }
        // B: 128 rows x 64 halves -> 1024 x 16B
#pragma unroll
        for (int i = 0; i < 4; i++) {
            int idx = tid + i * 256;
            int row = idx >> 3, seg = idx & 7;
            cpa16(bbase + (uint32_t)(row * (LDH * 2) + seg * 16),
                  W + (size_t)(bn + row) * K + k0 + seg * 8, 16);
        }
        asm volatile("cp.async.commit_group;\n");
    };

    issue(0, 0); issue(1, 1); issue(2, 2);

    for (int kt = 0; kt < KT; kt++) {
        const int st = kt % 3;
        if (kt < KT - 2)       asm volatile("cp.async.wait_group 2;\n");
        else if (kt == KT - 2) asm volatile("cp.async.wait_group 1;\n");
        else                   asm volatile("cp.async.wait_group 0;\n");
        __syncthreads();

        const __half* As = sm + st * STAGE_HALVES;
        const __half* Bs = As + A_HALVES;

#pragma unroll
        for (int s16 = 0; s16 < 4; s16++) {
            const int kk = s16 * 16 + tq * 2;   // half index (even -> 4B aligned)
            uint32_t af[4][4], bf[4][2];
#pragma unroll
            for (int nt = 0; nt < 4; nt++) {
                const __half* bp = Bs + (wn + nt * 8 + g) * LDH + kk;
                bf[nt][0] = *(const uint32_t*)(bp);
                bf[nt][1] = *(const uint32_t*)(bp + 8);
            }
#pragma unroll
            for (int mt = 0; mt < 4; mt++) {
                const __half* ap = As + (wm + mt * 16 + g) * LDH + kk;
                af[mt][0] = *(const uint32_t*)(ap);
                af[mt][1] = *(const uint32_t*)(ap + 8 * LDH);
                af[mt][2] = *(const uint32_t*)(ap + 8);
                af[mt][3] = *(const uint32_t*)(ap + 8 * LDH + 8);
            }
#pragma unroll
            for (int mt = 0; mt < 4; mt++)
#pragma unroll
                for (int nt = 0; nt < 4; nt++)
                    mma_f16(acc[mt][nt], af[mt], bf[nt]);
        }
        __syncthreads();

        const int kn = kt + 3;
        if (kn < KT) issue(kn, st);
    }

    // Epilogue: c0,c1 -> (row g, col tq*2..+1); c2,c3 -> row g+8
#pragma unroll
    for (int mt = 0; mt < 4; mt++) {
        const int r0 = bm + wm + mt * 16 + g;
#pragma unroll
        for (int nt = 0; nt < 4; nt++) {
            const int col = bn + wn + nt * 8 + tq * 2;
            if (EPI == 3) {
                // fused RG-LRU gate: col pair (2d, 2d+1) = (rl, il) for channel d
                const int d = col >> 1;
                const float ba_ = __ldg(bap + d);
                const float bx_ = __ldg(bxp + d);
                const float sp_ = __ldg(spp + d);
                const float hc0 = __half2float(hcp[(size_t)r0 * RR + d]);
                const float hc8 = __half2float(hcp[(size_t)(r0 + 8) * RR + d]);
                float rl0 = acc[mt][nt][0] + ba_, il0 = acc[mt][nt][1] + bx_;
                float rl8 = acc[mt][nt][2] + ba_, il8 = acc[mt][nt][3] + bx_;
                float a0 = __expf(sp_ / (1.f + __expf(-rl0)));
                float a8 = __expf(sp_ / (1.f + __expf(-rl8)));
                float b0 = sqrtf(fmaxf(1.f - a0 * a0, 0.f)) * hc0 / (1.f + __expf(-il0));
                float b8 = sqrtf(fmaxf(1.f - a8 * a8, 0.f)) * hc8 / (1.f + __expf(-il8));
                ((float*)C)[(size_t)r0 * RR + d]       = a0;
                ((float*)C)[(size_t)(r0 + 8) * RR + d] = a8;
                Gb[(size_t)r0 * RR + d]       = b0;
                Gb[(size_t)(r0 + 8) * RR + d] = b8;
            } else {
                float bx_ = 0.f, by_ = 0.f;
                if (BIAS) { float2 bb = *(const float2*)(bias + col); bx_ = bb.x; by_ = bb.y; }
                float v[4] = { acc[mt][nt][0] + bx_, acc[mt][nt][1] + by_,
                               acc[mt][nt][2] + bx_, acc[mt][nt][3] + by_ };
                if (EPI == 1) {
#pragma unroll
                    for (int j = 0; j < 4; j++) v[j] = v[j] / (1.f + __expf(-v[j]));
                }
                if (sizeof(TOUT) == 2) {
                    __half2* c0 = (__half2*)((__half*)C + (size_t)r0 * N + col);
                    __half2* c1 = (__half2*)((__half*)C + (size_t)(r0 + 8) * N + col);
                    *c0 = __floats2half2_rn(v[0], v[1]);
                    *c1 = __floats2half2_rn(v[2], v[3]);
                } else {
                    *(float2*)((float*)C + (size_t)r0 * N + col)       = make_float2(v[0], v[1]);
                    *(float2*)((float*)C + (size_t)(r0 + 8) * N + col) = make_float2(v[2], v[3]);
                }
            }
        }
    }
}

// ---------------------------------------------------------------------------
// prep / elementwise kernels
// ---------------------------------------------------------------------------
__global__ void half_copy(const float* __restrict__ in, __half* __restrict__ out, int n)
{
    int i = blockIdx.x * 256 + threadIdx.x;
    if (i < n) out[i] = __float2half_rn(in[i]);
}

// interleave wa/wx rows: out row 2d = wa_d, row 2d+1 = wx_d
__global__ void pack_gates(const float* __restrict__ wa, const float* __restrict__ wx,
                           __half* __restrict__ out)
{
    int idx = blockIdx.x * 256 + threadIdx.x;       // 2*RR*RR total (multiple of 256)
    int j = idx / RR;
    int k = idx - j * RR;
    const float* src = (j & 1) ? wx : wa;
    out[idx] = __float2half_rn(src[(size_t)(j >> 1) * RR + k]);
}

__global__ void conv_pack(const float* __restrict__ cw, __half* __restrict__ wch)
{
    int idx = blockIdx.x * 256 + threadIdx.x;
    int o   = idx / K4;
    int rem = idx - o * K4;
    int t   = rem / RR;
    int i   = rem - t * RR;
    wch[idx] = __float2half_rn(cw[((size_t)o * RR + i) * 4 + t]);
}

__global__ void prep_sp(const float* __restrict__ lam, float* __restrict__ sp)
{
    int d = blockIdx.x * 256 + threadIdx.x;
    if (d < RR) {
        float l = lam[d];
        float s = (l > 20.f) ? l : log1pf(expf(l));
        sp[d] = -8.f * s;
    }
}

// ---- 3-phase chunked scan: L=2048 -> 32 chunks x 64 steps ----
#define SCH 32
#define SCL 64

__global__ void scan_p1(const float* __restrict__ a, const float* __restrict__ bv,
                        float* __restrict__ CA, float* __restrict__ CB)
{
    int gid = blockIdx.x * 256 + threadIdx.x;          // BB*SCH*RR total
    int b   = gid / (SCH * RR);
    int rem = gid - b * (SCH * RR);
    int c   = rem / RR;
    int d   = rem - c * RR;
    size_t base = ((size_t)b * LL + (size_t)c * SCL) * RR + d;
    float Ap = 1.f, h = 0.f;
#pragma unroll 4
    for (int t = 0; t < SCL; t++) {
        size_t off = base + (size_t)t * RR;
        float at = a[off];
        Ap *= at;
        h = fmaf(at, h, bv[off]);
    }
    CA[gid] = Ap;
    CB[gid] = h;
}

__global__ void scan_p2(float* __restrict__ CA, float* __restrict__ CB)
{
    int gid = blockIdx.x * 256 + threadIdx.x;          // BB*RR total
    int b = gid / RR;
    int d = gid - b * RR;
    float h = 0.f;
#pragma unroll
    for (int c = 0; c < SCH; c++) {
        size_t idx = ((size_t)b * SCH + c) * RR + d;
        float A = CA[idx], Bv = CB[idx];
        CB[idx] = h;                 // carry-in for chunk c
        h = fmaf(A, h, Bv);
    }
}

__global__ void scan_p3(const float* __restrict__ a, const float* __restrict__ bv,
                        const float* __restrict__ CB, __half* __restrict__ h)
{
    int gid = blockIdx.x * 256 + threadIdx.x;
    int b   = gid / (SCH * RR);
    int rem = gid - b * (SCH * RR);
    int c   = rem / RR;
    int d   = rem - c * RR;
    size_t base = ((size_t)b * LL + (size_t)c * SCL) * RR + d;
    float hp = CB[gid];
#pragma unroll 4
    for (int t = 0; t < SCL; t++) {
        size_t off = base + (size_t)t * RR;
        hp = fmaf(a[off], hp, bv[off]);
        h[off] = __float2half_rn(hp);
    }
}

// ---------------------------------------------------------------------------
extern "C" void kernel_launch(void* const* d_in, const int* in_sizes, int n_in,
                              void* d_out, int out_size)
{
    const float* x      = (const float*)d_in[0];
    const float* w1     = (const float*)d_in[1];
    const float* b1     = (const float*)d_in[2];
    const float* conv_w = (const float*)d_in[3];
    const float* conv_b = (const float*)d_in[4];
    const float* wa     = (const float*)d_in[5];
    const float* ba     = (const float*)d_in[6];
    const float* wx     = (const float*)d_in[7];
    const float* bx     = (const float*)d_in[8];
    const float* lam    = (const float*)d_in[9];
    const float* w2     = (const float*)d_in[10];
    const float* b2     = (const float*)d_in[11];
    float* out = (float*)d_out;

    __half *W1h, *Wgh, *W2h, *Wch, *Xh, *H1h, *HCh;
    float  *Ga, *Gb, *CA, *CB, *sp;
    cudaGetSymbolAddress((void**)&W1h, g_W1h);
    cudaGetSymbolAddress((void**)&Wgh, g_Wgh);
    cudaGetSymbolAddress((void**)&W2h, g_W2h);
    cudaGetSymbolAddress((void**)&Wch, g_Wch);
    cudaGetSymbolAddress((void**)&Xh,  g_Xh);
    cudaGetSymbolAddress((void**)&H1h, g_H1h);
    cudaGetSymbolAddress((void**)&HCh, g_HCh);
    cudaGetSymbolAddress((void**)&Ga,  g_Ga);
    cudaGetSymbolAddress((void**)&Gb,  g_Gb);
    cudaGetSymbolAddress((void**)&CA,  g_CA);
    cudaGetSymbolAddress((void**)&CB,  g_CB);
    cudaGetSymbolAddress((void**)&sp,  g_sp);

    cudaFuncSetAttribute(gemm_mma<1, true,  false, __half>, cudaFuncAttributeMaxDynamicSharedMemorySize, GSMEM_TOTAL);
    cudaFuncSetAttribute(gemm_mma<0, true,  true,  __half>, cudaFuncAttributeMaxDynamicSharedMemorySize, GSMEM_TOTAL);
    cudaFuncSetAttribute(gemm_mma<3, false, false, float >, cudaFuncAttributeMaxDynamicSharedMemorySize, GSMEM_TOTAL);
    cudaFuncSetAttribute(gemm_mma<0, true,  false, float >, cudaFuncAttributeMaxDynamicSharedMemorySize, GSMEM_TOTAL);

    // prep: RN-round every MMA input to fp16 once
    half_copy<<<(RR * DD + 255) / 256, 256>>>(w1, W1h, RR * DD);
    pack_gates<<<(2 * RR * RR) / 256, 256>>>(wa, wx, Wgh);
    half_copy<<<(DD * RR + 255) / 256, 256>>>(w2, W2h, DD * RR);
    half_copy<<<(MM * DD + 255) / 256, 256>>>(x,  Xh,  MM * DD);
    conv_pack<<<((size_t)RR * K4) / 256, 256>>>(conv_w, Wch);
    prep_sp<<<(RR + 255) / 256, 256>>>(lam, sp);

    dim3 blk(256);
    dim3 gN2560(RR / TBN,     MM / 128);   // 20 x 64 = 1280
    dim3 gN5120(2 * RR / TBN, MM / 128);   // 40 x 64 = 2560
    dim3 gN2048(DD / TBN,     MM / 128);   // 16 x 64 = 1024

    // 1) H1 = h( silu(x @ w1^T + b1) )
    gemm_mma<1, true,  false, __half><<<gN2560, blk, GSMEM_TOTAL>>>(
        Xh, W1h, b1, H1h, RR, DD, DD, nullptr, nullptr, nullptr, nullptr, nullptr);
    // 2) HC = h( conv(H1) + conv_b )  — single fused GEMM, K = 4*R
    gemm_mma<0, true,  true,  __half><<<gN2560, blk, GSMEM_TOTAL>>>(
        H1h, Wch, conv_b, HCh, RR, K4, RR, nullptr, nullptr, nullptr, nullptr, nullptr);
    // 3+4) Ga/Gb = fused( HC @ [wa|wx interleaved]^T , gate math )
    gemm_mma<3, false, false, float ><<<gN5120, blk, GSMEM_TOTAL>>>(
        HCh, Wgh, nullptr, Ga, 2 * RR, RR, RR, HCh, sp, ba, bx, Gb);
    // 5) chunked parallel scan -> h (half, into H1h)
    scan_p1<<<(BB * SCH * RR) / 256, 256>>>(Ga, Gb, CA, CB);
    scan_p2<<<(BB * RR) / 256, 256>>>(CA, CB);
    scan_p3<<<(BB * SCH * RR) / 256, 256>>>(Ga, Gb, CB, H1h);
    // 6) out = h @ w2^T + b2  (f32)
    gemm_mma<0, true,  false, float ><<<gN2048, blk, GSMEM_TOTAL>>>(
        H1h, W2h, b2, out, DD, RR, RR, nullptr, nullptr, nullptr, nullptr, nullptr);
}

// round 10
// speedup vs baseline: 2.0743x; 1.0408x over previous
#include <cuda_runtime.h>
#include <cuda_fp16.h>
#include <math.h>
#include <stdint.h>

// Problem dims (fixed by the dataset)
#define BB 4
#define LL 2048
#define DD 2048
#define RR 2560
#define MM (BB * LL)      // 8192
#define K4 (4 * RR)       // 10240 (conv fused-K)

// ---------------------------------------------------------------------------
// Device scratch
// ---------------------------------------------------------------------------
__device__ __half g_W1h[(size_t)RR * DD];
__device__ __half g_Wgh[(size_t)2 * RR * RR];  // interleaved: row 2d=wa_d, 2d+1=wx_d
__device__ __half g_W2h[(size_t)DD * RR];
__device__ __half g_Wch[(size_t)RR * K4];
__device__ __half g_Xh [(size_t)MM * DD];
__device__ __half g_H1h[(size_t)MM * RR];     // silu out; later reused for scan h
__device__ __half g_HCh[(size_t)MM * RR];     // conv out
__device__ float  g_Ga [(size_t)MM * RR];
__device__ float  g_Gb [(size_t)MM * RR];
__device__ float  g_CA [(size_t)BB * 32 * RR];
__device__ float  g_CB [(size_t)BB * 32 * RR];
__device__ float  g_sp [RR];

// ---------------------------------------------------------------------------
// helpers / PTX  (base ISA only: mma.sync fp16 + cp.async)
// ---------------------------------------------------------------------------
__device__ __forceinline__ void cpa16(uint32_t dst, const void* src, int sz) {
    asm volatile("cp.async.cg.shared.global [%0], [%1], 16, %2;\n"
                 :: "r"(dst), "l"(src), "r"(sz));
}
__device__ __forceinline__ void mma_f16(float* c, const uint32_t* a, const uint32_t* b) {
    asm volatile(
        "mma.sync.aligned.m16n8k16.row.col.f32.f16.f16.f32 "
        "{%0,%1,%2,%3}, {%4,%5,%6,%7}, {%8,%9}, {%0,%1,%2,%3};\n"
        : "+f"(c[0]), "+f"(c[1]), "+f"(c[2]), "+f"(c[3])
        : "r"(a[0]), "r"(a[1]), "r"(a[2]), "r"(a[3]), "r"(b[0]), "r"(b[1]));
}

// ---------------------------------------------------------------------------
// fp16 tensor-core TN GEMM: C[M,N] = A[M,K] @ W[N,K]^T (+bias)(epilogue)
// CTA tile 128(M) x 128(N) x 64(K halves), 256 threads = 8 warps (2m x 4n),
// warp tile 64x32 (4x4 m16n8k16), 3-stage cp.async pipeline, 2 CTAs/SM.
// CONV: A is a 4-tap time-shifted view of H1 (K=4*RR, lda=RR), zero-padded.
// EPI: 0=none, 1=SiLU, 3=fused RG-LRU gate (writes Ga=C and Gb).
// ---------------------------------------------------------------------------
#define TBN 128
#define TKH 64                          // K halves per tile (=128B rows)
#define LDH 72                          // padded lead dim (halves), 144B
#define A_HALVES (128 * LDH)            // 9216
#define B_HALVES (TBN * LDH)            // 9216
#define STAGE_HALVES (A_HALVES + B_HALVES)
#define STAGE_BYTES  (STAGE_HALVES * 2)          // 36864
#define GSMEM_TOTAL  (3 * STAGE_BYTES)           // 110592 -> 2 CTAs/SM

template<int EPI, bool BIAS, bool CONV, typename TOUT>
__global__ __launch_bounds__(256, 2)
void gemm_mma(const __half* __restrict__ A, const __half* __restrict__ W,
              const float* __restrict__ bias, TOUT* __restrict__ C,
              int N, int K, int lda,
              const __half* __restrict__ hcp, const float* __restrict__ spp,
              const float* __restrict__ bap, const float* __restrict__ bxp,
              float* __restrict__ Gb)
{
    extern __shared__ __half sm[];
    const uint32_t smb = (uint32_t)__cvta_generic_to_shared(sm);

    const int tid  = threadIdx.x;
    const int lane = tid & 31;
    const int wid  = tid >> 5;
    const int g    = lane >> 2;         // 0..7
    const int tq   = lane & 3;          // 0..3
    const int wm   = (wid >> 2) << 6;   // 0 / 64
    const int wn   = (wid & 3) << 5;    // 0,32,64,96
    const int bm   = blockIdx.y * 128;
    const int bn   = blockIdx.x * TBN;

    float acc[4][4][4];
#pragma unroll
    for (int i = 0; i < 4; i++)
#pragma unroll
        for (int j = 0; j < 4; j++)
#pragma unroll
            for (int c = 0; c < 4; c++) acc[i][j][c] = 0.f;

    const int KT = K / TKH;

    auto issue = [&](int kt, int st) {
        const int k0 = kt * TKH;
        int tap = 0, shift = 0, kcol = k0;
        if (CONV) { tap = k0 / RR; kcol = k0 - tap * RR; shift = 2 * tap - 3; }
        const uint32_t abase = smb + st * STAGE_BYTES;
        const uint32_t bbase = abase + A_HALVES * 2;
        // A: 128 rows x 64 halves (128B) -> 1024 x 16B
#pragma unroll
        for (int i = 0; i < 4; i++) {
            int idx = tid + i * 256;
            int row = idx >> 3, seg = idx & 7;
            int m = bm + row, arow = m, sz = 16;
            if (CONV) {
                int t  = m & (LL - 1);
                int ts = t + shift;
                if ((unsigned)ts < (unsigned)LL) arow = m - t + ts;
                else                             sz = 0;     // zero-fill pad row
            }
            cpa16(abase + (uint32_t)(row * (LDH * 2) + seg * 16),
                  A + (size_t)arow * lda + kcol + seg * 8, sz);
        }
        // B: 128 rows x 64 halves -> 1024 x 16B
#pragma unroll
        for (int i = 0; i < 4; i++) {
            int idx = tid + i * 256;
            int row = idx >> 3, seg = idx & 7;
            cpa16(bbase + (uint32_t)(row * (LDH * 2) + seg * 16),
                  W + (size_t)(bn + row) * K + k0 + seg * 8, 16);
        }
        asm volatile("cp.async.commit_group;\n");
    };

    issue(0, 0); issue(1, 1); issue(2, 2);

    for (int kt = 0; kt < KT; kt++) {
        const int st = kt % 3;
        if (kt < KT - 2)       asm volatile("cp.async.wait_group 2;\n");
        else if (kt == KT - 2) asm volatile("cp.async.wait_group 1;\n");
        else                   asm volatile("cp.async.wait_group 0;\n");
        __syncthreads();

        const __half* As = sm + st * STAGE_HALVES;
        const __half* Bs = As + A_HALVES;

#pragma unroll
        for (int s16 = 0; s16 < 4; s16++) {
            const int kk = s16 * 16 + tq * 2;   // half index (even -> 4B aligned)
            uint32_t af[4][4], bf[4][2];
#pragma unroll
            for (int nt = 0; nt < 4; nt++) {
                const __half* bp = Bs + (wn + nt * 8 + g) * LDH + kk;
                bf[nt][0] = *(const uint32_t*)(bp);
                bf[nt][1] = *(const uint32_t*)(bp + 8);
            }
#pragma unroll
            for (int mt = 0; mt < 4; mt++) {
                const __half* ap = As + (wm + mt * 16 + g) * LDH + kk;
                af[mt][0] = *(const uint32_t*)(ap);
                af[mt][1] = *(const uint32_t*)(ap + 8 * LDH);
                af[mt][2] = *(const uint32_t*)(ap + 8);
                af[mt][3] = *(const uint32_t*)(ap + 8 * LDH + 8);
            }
#pragma unroll
            for (int mt = 0; mt < 4; mt++)
#pragma unroll
                for (int nt = 0; nt < 4; nt++)
                    mma_f16(acc[mt][nt], af[mt], bf[nt]);
        }
        __syncthreads();

        const int kn = kt + 3;
        if (kn < KT) issue(kn, st);
    }

    // Epilogue: c0,c1 -> (row g, col tq*2..+1); c2,c3 -> row g+8
#pragma unroll
    for (int mt = 0; mt < 4; mt++) {
        const int r0 = bm + wm + mt * 16 + g;
#pragma unroll
        for (int nt = 0; nt < 4; nt++) {
            const int col = bn + wn + nt * 8 + tq * 2;
            if (EPI == 3) {
                // fused RG-LRU gate: col pair (2d, 2d+1) = (rl, il) for channel d
                const int d = col >> 1;
                const float ba_ = __ldg(bap + d);
                const float bx_ = __ldg(bxp + d);
                const float sp_ = __ldg(spp + d);
                const float hc0 = __half2float(hcp[(size_t)r0 * RR + d]);
                const float hc8 = __half2float(hcp[(size_t)(r0 + 8) * RR + d]);
                float rl0 = acc[mt][nt][0] + ba_, il0 = acc[mt][nt][1] + bx_;
                float rl8 = acc[mt][nt][2] + ba_, il8 = acc[mt][nt][3] + bx_;
                float a0 = __expf(sp_ / (1.f + __expf(-rl0)));
                float a8 = __expf(sp_ / (1.f + __expf(-rl8)));
                float b0 = sqrtf(fmaxf(1.f - a0 * a0, 0.f)) * hc0 / (1.f + __expf(-il0));
                float b8 = sqrtf(fmaxf(1.f - a8 * a8, 0.f)) * hc8 / (1.f + __expf(-il8));
                ((float*)C)[(size_t)r0 * RR + d]       = a0;
                ((float*)C)[(size_t)(r0 + 8) * RR + d] = a8;
                Gb[(size_t)r0 * RR + d]       = b0;
                Gb[(size_t)(r0 + 8) * RR + d] = b8;
            } else {
                float bx_ = 0.f, by_ = 0.f;
                if (BIAS) { float2 bb = *(const float2*)(bias + col); bx_ = bb.x; by_ = bb.y; }
                float v[4] = { acc[mt][nt][0] + bx_, acc[mt][nt][1] + by_,
                               acc[mt][nt][2] + bx_, acc[mt][nt][3] + by_ };
                if (EPI == 1) {
#pragma unroll
                    for (int j = 0; j < 4; j++) v[j] = v[j] / (1.f + __expf(-v[j]));
                }
                if (sizeof(TOUT) == 2) {
                    __half2* c0 = (__half2*)((__half*)C + (size_t)r0 * N + col);
                    __half2* c1 = (__half2*)((__half*)C + (size_t)(r0 + 8) * N + col);
                    *c0 = __floats2half2_rn(v[0], v[1]);
                    *c1 = __floats2half2_rn(v[2], v[3]);
                } else {
                    *(float2*)((float*)C + (size_t)r0 * N + col)       = make_float2(v[0], v[1]);
                    *(float2*)((float*)C + (size_t)(r0 + 8) * N + col) = make_float2(v[2], v[3]);
                }
            }
        }
    }
}

// ---------------------------------------------------------------------------
// prep kernels (vectorized: float4 reads, packed half writes)
// ---------------------------------------------------------------------------
__device__ __forceinline__ uint32_t h2bits(float a, float b) {
    __half2 h = __floats2half2_rn(a, b);
    return *(const uint32_t*)&h;
}

// 8 floats -> 8 halves per thread (16B in x2, 16B out)
__global__ void half_copy8(const float4* __restrict__ in, uint4* __restrict__ out)
{
    size_t i = (size_t)blockIdx.x * 256 + threadIdx.x;
    float4 a = in[2 * i], b = in[2 * i + 1];
    uint4 o;
    o.x = h2bits(a.x, a.y); o.y = h2bits(a.z, a.w);
    o.z = h2bits(b.x, b.y); o.w = h2bits(b.z, b.w);
    out[i] = o;
}

// interleave wa/wx rows, 4 cols per thread: out row 2d=wa_d, 2d+1=wx_d
__global__ void pack_gates4(const float* __restrict__ wa, const float* __restrict__ wx,
                            uint2* __restrict__ out)
{
    int idx = blockIdx.x * 256 + threadIdx.x;      // j*(RR/4)+q, 2*RR*RR/4 total
    int j = idx / (RR / 4);
    int q = idx - j * (RR / 4);
    const float4* src = (const float4*)((j & 1) ? wx : wa) + (size_t)(j >> 1) * (RR / 4) + q;
    float4 v = *src;
    uint2 o;
    o.x = h2bits(v.x, v.y); o.y = h2bits(v.z, v.w);
    out[idx] = o;
}

// conv_w [o][i][t] -> Wch [o][t*R + i]; float4 read = all 4 taps of (o,i)
__global__ void conv_pack4(const float4* __restrict__ cw4, __half* __restrict__ wch)
{
    int T = blockIdx.x * 256 + threadIdx.x;        // o*RR + i, RR*RR total
    int o = T / RR;
    int i = T - o * RR;
    float4 v = cw4[T];
    size_t base = (size_t)o * K4 + i;
    wch[base]          = __float2half_rn(v.x);
    wch[base + RR]     = __float2half_rn(v.y);
    wch[base + 2 * RR] = __float2half_rn(v.z);
    wch[base + 3 * RR] = __float2half_rn(v.w);
}

__global__ void prep_sp(const float* __restrict__ lam, float* __restrict__ sp)
{
    int d = blockIdx.x * 256 + threadIdx.x;
    if (d < RR) {
        float l = lam[d];
        float s = (l > 20.f) ? l : log1pf(expf(l));
        sp[d] = -8.f * s;
    }
}

// ---- 3-phase chunked scan: L=2048 -> 32 chunks x 64 steps ----
#define SCH 32
#define SCL 64

__global__ void scan_p1(const float* __restrict__ a, const float* __restrict__ bv,
                        float* __restrict__ CA, float* __restrict__ CB)
{
    int gid = blockIdx.x * 256 + threadIdx.x;          // BB*SCH*RR total
    int b   = gid / (SCH * RR);
    int rem = gid - b * (SCH * RR);
    int c   = rem / RR;
    int d   = rem - c * RR;
    size_t base = ((size_t)b * LL + (size_t)c * SCL) * RR + d;
    float Ap = 1.f, h = 0.f;
#pragma unroll 4
    for (int t = 0; t < SCL; t++) {
        size_t off = base + (size_t)t * RR;
        float at = a[off];
        Ap *= at;
        h = fmaf(at, h, bv[off]);
    }
    CA[gid] = Ap;
    CB[gid] = h;
}

__global__ void scan_p2(float* __restrict__ CA, float* __restrict__ CB)
{
    int gid = blockIdx.x * 256 + threadIdx.x;          // BB*RR total
    int b = gid / RR;
    int d = gid - b * RR;
    float h = 0.f;
#pragma unroll
    for (int c = 0; c < SCH; c++) {
        size_t idx = ((size_t)b * SCH + c) * RR + d;
        float A = CA[idx], Bv = CB[idx];
        CB[idx] = h;                 // carry-in for chunk c
        h = fmaf(A, h, Bv);
    }
}

__global__ void scan_p3(const float* __restrict__ a, const float* __restrict__ bv,
                        const float* __restrict__ CB, __half* __restrict__ h)
{
    int gid = blockIdx.x * 256 + threadIdx.x;
    int b   = gid / (SCH * RR);
    int rem = gid - b * (SCH * RR);
    int c   = rem / RR;
    int d   = rem - c * RR;
    size_t base = ((size_t)b * LL + (size_t)c * SCL) * RR + d;
    float hp = CB[gid];
#pragma unroll 4
    for (int t = 0; t < SCL; t++) {
        size_t off = base + (size_t)t * RR;
        hp = fmaf(a[off], hp, bv[off]);
        h[off] = __float2half_rn(hp);
    }
}

// ---------------------------------------------------------------------------
extern "C" void kernel_launch(void* const* d_in, const int* in_sizes, int n_in,
                              void* d_out, int out_size)
{
    const float* x      = (const float*)d_in[0];
    const float* w1     = (const float*)d_in[1];
    const float* b1     = (const float*)d_in[2];
    const float* conv_w = (const float*)d_in[3];
    const float* conv_b = (const float*)d_in[4];
    const float* wa     = (const float*)d_in[5];
    const float* ba     = (const float*)d_in[6];
    const float* wx     = (const float*)d_in[7];
    const float* bx     = (const float*)d_in[8];
    const float* lam    = (const float*)d_in[9];
    const float* w2     = (const float*)d_in[10];
    const float* b2     = (const float*)d_in[11];
    float* out = (float*)d_out;

    __half *W1h, *Wgh, *W2h, *Wch, *Xh, *H1h, *HCh;
    float  *Ga, *Gb, *CA, *CB, *sp;
    cudaGetSymbolAddress((void**)&W1h, g_W1h);
    cudaGetSymbolAddress((void**)&Wgh, g_Wgh);
    cudaGetSymbolAddress((void**)&W2h, g_W2h);
    cudaGetSymbolAddress((void**)&Wch, g_Wch);
    cudaGetSymbolAddress((void**)&Xh,  g_Xh);
    cudaGetSymbolAddress((void**)&H1h, g_H1h);
    cudaGetSymbolAddress((void**)&HCh, g_HCh);
    cudaGetSymbolAddress((void**)&Ga,  g_Ga);
    cudaGetSymbolAddress((void**)&Gb,  g_Gb);
    cudaGetSymbolAddress((void**)&CA,  g_CA);
    cudaGetSymbolAddress((void**)&CB,  g_CB);
    cudaGetSymbolAddress((void**)&sp,  g_sp);

    cudaFuncSetAttribute(gemm_mma<1, true,  false, __half>, cudaFuncAttributeMaxDynamicSharedMemorySize, GSMEM_TOTAL);
    cudaFuncSetAttribute(gemm_mma<0, true,  true,  __half>, cudaFuncAttributeMaxDynamicSharedMemorySize, GSMEM_TOTAL);
    cudaFuncSetAttribute(gemm_mma<3, false, false, float >, cudaFuncAttributeMaxDynamicSharedMemorySize, GSMEM_TOTAL);
    cudaFuncSetAttribute(gemm_mma<0, true,  false, float >, cudaFuncAttributeMaxDynamicSharedMemorySize, GSMEM_TOTAL);

    // side stream + fork/join events (created once; host-side objects only)
    static cudaStream_t s2 = nullptr;
    static cudaEvent_t evFork = nullptr, evJoin = nullptr;
    if (!s2) {
        cudaStreamCreateWithFlags(&s2, cudaStreamNonBlocking);
        cudaEventCreateWithFlags(&evFork, cudaEventDisableTiming);
        cudaEventCreateWithFlags(&evJoin, cudaEventDisableTiming);
    }

    // fork: weight prep for later GEMMs runs concurrently with x-prep + gemm1
    cudaEventRecord(evFork, 0);
    cudaStreamWaitEvent(s2, evFork, 0);
    conv_pack4<<<(RR * RR) / 256, 256, 0, s2>>>((const float4*)conv_w, Wch);
    pack_gates4<<<(2 * RR * RR / 4) / 256, 256, 0, s2>>>(wa, wx, (uint2*)Wgh);
    half_copy8<<<((size_t)DD * RR / 8) / 256, 256, 0, s2>>>((const float4*)w2, (uint4*)W2h);
    prep_sp<<<(RR + 255) / 256, 256, 0, s2>>>(lam, sp);
    cudaEventRecord(evJoin, s2);

    // main stream: inputs for gemm1
    half_copy8<<<((size_t)MM * DD / 8) / 256, 256>>>((const float4*)x,  (uint4*)Xh);
    half_copy8<<<((size_t)RR * DD / 8) / 256, 256>>>((const float4*)w1, (uint4*)W1h);

    dim3 blk(256);
    dim3 gN2560(RR / TBN,     MM / 128);   // 20 x 64 = 1280
    dim3 gN5120(2 * RR / TBN, MM / 128);   // 40 x 64 = 2560
    dim3 gN2048(DD / TBN,     MM / 128);   // 16 x 64 = 1024

    // 1) H1 = h( silu(x @ w1^T + b1) )
    gemm_mma<1, true,  false, __half><<<gN2560, blk, GSMEM_TOTAL>>>(
        Xh, W1h, b1, H1h, RR, DD, DD, nullptr, nullptr, nullptr, nullptr, nullptr);

    // join: Wch/Wgh/W2h/sp ready before they are consumed
    cudaStreamWaitEvent(0, evJoin, 0);

    // 2) HC = h( conv(H1) + conv_b )  — single fused GEMM, K = 4*R
    gemm_mma<0, true,  true,  __half><<<gN2560, blk, GSMEM_TOTAL>>>(
        H1h, Wch, conv_b, HCh, RR, K4, RR, nullptr, nullptr, nullptr, nullptr, nullptr);
    // 3+4) Ga/Gb = fused( HC @ [wa|wx interleaved]^T , gate math )
    gemm_mma<3, false, false, float ><<<gN5120, blk, GSMEM_TOTAL>>>(
        HCh, Wgh, nullptr, Ga, 2 * RR, RR, RR, HCh, sp, ba, bx, Gb);
    // 5) chunked parallel scan -> h (half, into H1h)
    scan_p1<<<(BB * SCH * RR) / 256, 256>>>(Ga, Gb, CA, CB);
    scan_p2<<<(BB * RR) / 256, 256>>>(CA, CB);
    scan_p3<<<(BB * SCH * RR) / 256, 256>>>(Ga, Gb, CB, H1h);
    // 6) out = h @ w2^T + b2  (f32)
    gemm_mma<0, true,  false, float ><<<gN2048, blk, GSMEM_TOTAL>>>(
        H1h, W2h, b2, out, DD, RR, RR, nullptr, nullptr, nullptr, nullptr, nullptr);
}